// round 5
// baseline (speedup 1.0000x reference)
#include <cuda_runtime.h>
#include <cstdint>

// GCN FeatureDiscriminator: B=256, V=512, F=256, O=2
// Pipelined: A (streaming, 4 chunks of 256 CTAs) with B (aggregation,
// 64 CTAs/chunk = 21% of device slots, low-priority stream) overlapped.
// Key fix vs round 4: B chunks can no longer flood the device, so A and B
// co-reside instead of alternating.

#define BATCH 256
#define BV 512
#define BF 256
#define NROWS (BATCH * BV)
#define NTHREADS 512
#define NWARP 16
#define NCHUNK 4
#define BATCH_PER_CHUNK (BATCH / NCHUNK)          // 64
#define ROWS_PER_CHUNK (NROWS / NCHUNK)           // 32768
#define GRID_A 256                                 // 4096 warps -> exactly 8 rows/warp/chunk
#define TOTAL_WARPS_A (GRID_A * NWARP)

__device__ unsigned g_bits[NROWS * 16];   // 8 MB: 512-bit mask per row
__device__ float    g_dinv[NROWS];
__device__ float2   g_sxw[NROWS];         // dinv[w] * (X[w,:] @ W)

// ---------------------------------------------------------------------------
// Kernel A: warp per row, grid-stride within chunk.
// Bit convention: bits[row][4c+k] bit 'l'  <->  column w = 128*c + 4*l + k
// ---------------------------------------------------------------------------
__global__ __launch_bounds__(NTHREADS, 2)
void gcn_rows_kernel(const float* __restrict__ features,
                     const int*   __restrict__ graphs,
                     const float* __restrict__ conv_weight,   // [F,2]
                     int row_base)
{
    const int tid  = threadIdx.x;
    const int wid  = tid >> 5;
    const int lane = tid & 31;
    const int gwarp = blockIdx.x * NWARP + wid;

    float w0r[8], w1r[8];
    {
        const float2* cw2 = (const float2*)conv_weight;
        #pragma unroll
        for (int j = 0; j < 8; j++) {
            float2 w = __ldg(cw2 + 8 * lane + j);
            w0r[j] = w.x; w1r[j] = w.y;
        }
    }

    const int row_end = row_base + ROWS_PER_CHUNK;
    for (int row = row_base + gwarp; row < row_end; row += TOTAL_WARPS_A) {
        const int v = row & (BV - 1);
        const int4*   grow = (const int4*)graphs + (size_t)row * (BV / 4);
        const float4* frow = (const float4*)features + (size_t)row * (BF / 4);

        int4 x0 = __ldcs(grow + 0 * 32 + lane);
        int4 x1 = __ldcs(grow + 1 * 32 + lane);
        int4 x2 = __ldcs(grow + 2 * 32 + lane);
        int4 x3 = __ldcs(grow + 3 * 32 + lane);
        float4 fa = __ldcs(frow + 2 * lane);
        float4 fb = __ldcs(frow + 2 * lane + 1);

        int deg = 0;
        #pragma unroll
        for (int c = 0; c < 4; c++) {
            int4 x = (c == 0) ? x0 : (c == 1) ? x1 : (c == 2) ? x2 : x3;
            int w0 = 128 * c + 4 * lane;
            unsigned m0 = __ballot_sync(0xffffffffu, (x.x != 0) || (w0     == v));
            unsigned m1 = __ballot_sync(0xffffffffu, (x.y != 0) || (w0 + 1 == v));
            unsigned m2 = __ballot_sync(0xffffffffu, (x.z != 0) || (w0 + 2 == v));
            unsigned m3 = __ballot_sync(0xffffffffu, (x.w != 0) || (w0 + 3 == v));
            deg += __popc(m0) + __popc(m1) + __popc(m2) + __popc(m3);
            if (lane == c) {
                ((uint4*)g_bits)[(size_t)row * 4 + c] = make_uint4(m0, m1, m2, m3);
            }
        }

        float acc0 = fa.x * w0r[0];             float acc1 = fa.x * w1r[0];
        acc0 = fmaf(fa.y, w0r[1], acc0);        acc1 = fmaf(fa.y, w1r[1], acc1);
        acc0 = fmaf(fa.z, w0r[2], acc0);        acc1 = fmaf(fa.z, w1r[2], acc1);
        acc0 = fmaf(fa.w, w0r[3], acc0);        acc1 = fmaf(fa.w, w1r[3], acc1);
        acc0 = fmaf(fb.x, w0r[4], acc0);        acc1 = fmaf(fb.x, w1r[4], acc1);
        acc0 = fmaf(fb.y, w0r[5], acc0);        acc1 = fmaf(fb.y, w1r[5], acc1);
        acc0 = fmaf(fb.z, w0r[6], acc0);        acc1 = fmaf(fb.z, w1r[6], acc1);
        acc0 = fmaf(fb.w, w0r[7], acc0);        acc1 = fmaf(fb.w, w1r[7], acc1);
        #pragma unroll
        for (int s = 16; s; s >>= 1) {
            acc0 += __shfl_xor_sync(0xffffffffu, acc0, s);
            acc1 += __shfl_xor_sync(0xffffffffu, acc1, s);
        }
        if (lane == 0) {
            float d = rsqrtf((float)deg);        // deg >= 1 (self-loop)
            g_dinv[row] = d;
            g_sxw[row]  = make_float2(d * acc0, d * acc1);
        }
    }
}

// ---------------------------------------------------------------------------
// Kernel B: one CTA per batch (round-2 proven path). 64 CTAs per chunk.
// ---------------------------------------------------------------------------
__global__ __launch_bounds__(NTHREADS, 2)
void gcn_agg_kernel(const float* __restrict__ conv_bias,
                    const float* __restrict__ lin_weight,   // [2v+o]
                    const float* __restrict__ lin_bias,
                    float* __restrict__ out,
                    int batch_base)
{
    __shared__ unsigned bits[BV][16];   // 32 KB
    __shared__ float s0[BV];
    __shared__ float s1[BV];
    __shared__ float dinv_s[BV];
    __shared__ float lw_s[BV * 2];
    __shared__ float wpart[NWARP];

    const int b    = batch_base + blockIdx.x;
    const int tid  = threadIdx.x;
    const int wid  = tid >> 5;
    const int lane = tid & 31;

    {
        const uint4* src = (const uint4*)g_bits + (size_t)b * (BV * 4);
        uint4* dst = (uint4*)bits;
        #pragma unroll
        for (int i = 0; i < 4; i++) dst[tid + i * NTHREADS] = src[tid + i * NTHREADS];

        float2 xw = g_sxw[b * BV + tid];           // already dinv-scaled
        s0[tid] = xw.x;
        s1[tid] = xw.y;
        dinv_s[tid] = g_dinv[b * BV + tid];

        lw_s[tid]            = lin_weight[tid];
        lw_s[tid + NTHREADS] = lin_weight[tid + NTHREADS];
    }
    __syncthreads();

    // preload this lane's fixed 16 s pairs: w = 128*c + 4*lane + k
    float r0[16], r1[16];
    #pragma unroll
    for (int c = 0; c < 4; c++)
        #pragma unroll
        for (int k = 0; k < 4; k++) {
            int w = 128 * c + 4 * lane + k;
            r0[4 * c + k] = s0[w];
            r1[4 * c + k] = s1[w];
        }

    const float cb0 = conv_bias[0];
    const float cb1 = conv_bias[1];

    float part = 0.0f;
    #pragma unroll 2
    for (int r = 0; r < BV / NWARP; r++) {
        const int v = wid * (BV / NWARP) + r;
        float acc0 = 0.0f, acc1 = 0.0f;
        #pragma unroll
        for (int j = 0; j < 16; j++) {
            unsigned m = bits[v][j];               // broadcast LDS
            if ((m >> lane) & 1u) {
                acc0 += r0[j];
                acc1 += r1[j];
            }
        }
        #pragma unroll
        for (int s = 16; s; s >>= 1) {
            acc0 += __shfl_xor_sync(0xffffffffu, acc0, s);
            acc1 += __shfl_xor_sync(0xffffffffu, acc1, s);
        }
        if (lane == 0) {
            float d  = dinv_s[v];
            float h0 = fmaxf(fmaf(d, acc0, cb0), 0.0f);
            float h1 = fmaxf(fmaf(d, acc1, cb1), 0.0f);
            part = fmaf(h0, lw_s[2 * v], part);
            part = fmaf(h1, lw_s[2 * v + 1], part);
        }
    }
    if (lane == 0) wpart[wid] = part;
    __syncthreads();

    if (wid == 0) {
        float s = (lane < NWARP) ? wpart[lane] : 0.0f;
        #pragma unroll
        for (int sh = 8; sh; sh >>= 1) s += __shfl_xor_sync(0xffffffffu, s, sh);
        if (lane == 0) {
            float logit = s + lin_bias[0];
            out[b] = 1.0f / (1.0f + expf(-logit));
        }
    }
}

extern "C" void kernel_launch(void* const* d_in, const int* in_sizes, int n_in,
                              void* d_out, int out_size) {
    const float* features    = (const float*)d_in[0];
    const int*   graphs      = (const int*)  d_in[1];
    const float* conv_weight = (const float*)d_in[2];
    const float* conv_bias   = (const float*)d_in[3];
    const float* lin_weight  = (const float*)d_in[4];
    const float* lin_bias    = (const float*)d_in[5];
    float* out = (float*)d_out;

    // one-time creation (first call is the uncaptured correctness run)
    static cudaStream_t s1;
    static cudaEvent_t evA[NCHUNK], evJoin;
    static int init_done = 0;
    if (!init_done) {
        int lo, hi;  // lo = least priority (numerically largest), hi = greatest
        cudaDeviceGetStreamPriorityRange(&lo, &hi);
        cudaStreamCreateWithPriority(&s1, cudaStreamNonBlocking, lo);
        for (int k = 0; k < NCHUNK; k++)
            cudaEventCreateWithFlags(&evA[k], cudaEventDisableTiming);
        cudaEventCreateWithFlags(&evJoin, cudaEventDisableTiming);
        init_done = 1;
    }

    for (int k = 0; k < NCHUNK; k++) {
        gcn_rows_kernel<<<GRID_A, NTHREADS>>>(features, graphs, conv_weight,
                                              k * ROWS_PER_CHUNK);
        cudaEventRecord(evA[k], 0);
        cudaStreamWaitEvent(s1, evA[k], 0);
        gcn_agg_kernel<<<BATCH_PER_CHUNK, NTHREADS, 0, s1>>>(
            conv_bias, lin_weight, lin_bias, out, k * BATCH_PER_CHUNK);
    }
    // join: the capture stream must depend on B's completion so the graph's
    // output is complete when the harness's replay finishes.
    cudaEventRecord(evJoin, s1);
    cudaStreamWaitEvent((cudaStream_t)0, evJoin, 0);
}

// round 6
// speedup vs baseline: 1.1238x; 1.1238x over previous
#include <cuda_runtime.h>
#include <cstdint>

// GCN FeatureDiscriminator: B=256, V=512, F=256, O=2
// Kernel A: balanced row-local streaming (graphs 256MB + features 128MB ->
//           bits 8MB, dinv, prescaled sxw).  [proven, ~60.5us]
// Kernel B: per-batch aggregation via nibble subset-sum LUT + transpose-reduce.

#define BATCH 256
#define BV 512
#define BF 256
#define NROWS (BATCH * BV)
#define NTHREADS 512
#define NWARP 16
#define GRID_A 304
#define TOTAL_WARPS_A (GRID_A * NWARP)

__device__ unsigned g_bits[NROWS * 16];   // 8 MB: 512-bit mask per row
__device__ float    g_dinv[NROWS];
__device__ float2   g_sxw[NROWS];         // dinv[w] * (X[w,:] @ W)

// packed fp32x2 helpers (plain adds only — no predication asm)
#define ADDX2(out, a, b) asm("add.rn.f32x2 %0, %1, %2;" : "=l"(out) : "l"(a), "l"(b))
#define PACKX2(out, lo, hi) asm("mov.b64 %0, {%1, %2};" : "=l"(out) : "r"(lo), "r"(hi))
#define UNPACKX2(lo, hi, in) asm("mov.b64 {%0, %1}, %2;" : "=r"(lo), "=r"(hi) : "l"(in))

// ---------------------------------------------------------------------------
// Kernel A: warp per row, grid-stride.
// Bit convention: bits[row][4c+k] bit 'l'  <->  column w = 128*c + 4*l + k
// ---------------------------------------------------------------------------
__global__ __launch_bounds__(NTHREADS, 2)
void gcn_rows_kernel(const float* __restrict__ features,
                     const int*   __restrict__ graphs,
                     const float* __restrict__ conv_weight)   // [F,2]
{
    const int tid  = threadIdx.x;
    const int wid  = tid >> 5;
    const int lane = tid & 31;
    const int gwarp = blockIdx.x * NWARP + wid;

    float w0r[8], w1r[8];
    {
        const float2* cw2 = (const float2*)conv_weight;
        #pragma unroll
        for (int j = 0; j < 8; j++) {
            float2 w = __ldg(cw2 + 8 * lane + j);
            w0r[j] = w.x; w1r[j] = w.y;
        }
    }

    for (int row = gwarp; row < NROWS; row += TOTAL_WARPS_A) {
        const int v = row & (BV - 1);
        const int4*   grow = (const int4*)graphs + (size_t)row * (BV / 4);
        const float4* frow = (const float4*)features + (size_t)row * (BF / 4);

        int4 x0 = __ldcs(grow + 0 * 32 + lane);
        int4 x1 = __ldcs(grow + 1 * 32 + lane);
        int4 x2 = __ldcs(grow + 2 * 32 + lane);
        int4 x3 = __ldcs(grow + 3 * 32 + lane);
        float4 fa = __ldcs(frow + 2 * lane);
        float4 fb = __ldcs(frow + 2 * lane + 1);

        int deg = 0;
        #pragma unroll
        for (int c = 0; c < 4; c++) {
            int4 x = (c == 0) ? x0 : (c == 1) ? x1 : (c == 2) ? x2 : x3;
            int w0 = 128 * c + 4 * lane;
            unsigned m0 = __ballot_sync(0xffffffffu, (x.x != 0) || (w0     == v));
            unsigned m1 = __ballot_sync(0xffffffffu, (x.y != 0) || (w0 + 1 == v));
            unsigned m2 = __ballot_sync(0xffffffffu, (x.z != 0) || (w0 + 2 == v));
            unsigned m3 = __ballot_sync(0xffffffffu, (x.w != 0) || (w0 + 3 == v));
            deg += __popc(m0) + __popc(m1) + __popc(m2) + __popc(m3);
            if (lane == c) {
                ((uint4*)g_bits)[(size_t)row * 4 + c] = make_uint4(m0, m1, m2, m3);
            }
        }

        float acc0 = fa.x * w0r[0];             float acc1 = fa.x * w1r[0];
        acc0 = fmaf(fa.y, w0r[1], acc0);        acc1 = fmaf(fa.y, w1r[1], acc1);
        acc0 = fmaf(fa.z, w0r[2], acc0);        acc1 = fmaf(fa.z, w1r[2], acc1);
        acc0 = fmaf(fa.w, w0r[3], acc0);        acc1 = fmaf(fa.w, w1r[3], acc1);
        acc0 = fmaf(fb.x, w0r[4], acc0);        acc1 = fmaf(fb.x, w1r[4], acc1);
        acc0 = fmaf(fb.y, w0r[5], acc0);        acc1 = fmaf(fb.y, w1r[5], acc1);
        acc0 = fmaf(fb.z, w0r[6], acc0);        acc1 = fmaf(fb.z, w1r[6], acc1);
        acc0 = fmaf(fb.w, w0r[7], acc0);        acc1 = fmaf(fb.w, w1r[7], acc1);
        #pragma unroll
        for (int s = 16; s; s >>= 1) {
            acc0 += __shfl_xor_sync(0xffffffffu, acc0, s);
            acc1 += __shfl_xor_sync(0xffffffffu, acc1, s);
        }
        if (lane == 0) {
            float d = rsqrtf((float)deg);        // deg >= 1 (self-loop)
            g_dinv[row] = d;
            g_sxw[row]  = make_float2(d * acc0, d * acc1);
        }
    }
}

// ---------------------------------------------------------------------------
// Kernel B: one CTA per batch. Nibble subset-sum LUT aggregation.
//
// Mask word j=4c+k, bit b  <->  w = 128c + 4b + k.
// Lane l owns bits 16l..16l+15 = word (l>>1), half (l&1).
// Nibble t (0..3) of lane l's field covers w = 128c + 64h + 16t + 4m + k,
// m=0..3, where j=l>>1, h=l&1, c=j>>2, k=j&3.  Position p = 4l+t (0..127).
// lut[p][nib] = sum over set bits m of s[w(p,m)], packed (s0,s1) in u64.
// ---------------------------------------------------------------------------
struct SmemB {
    unsigned bits[BV][16];                    // 32 KB
    unsigned long long lut[128 * 17];         // 17.4 KB (stride 17 vs bank conflicts)
    float2 s2[BV];                            // 4 KB
    float dinv_s[BV];                         // 2 KB
    float2 lw2[BV];                           // 4 KB
    unsigned long long buf[NWARP][8][33];     // 33.8 KB transpose-reduce
    float wpart[NWARP];
};                                            // ~94 KB

__global__ __launch_bounds__(NTHREADS, 2)
void gcn_agg_kernel(const float* __restrict__ conv_bias,
                    const float* __restrict__ lin_weight,   // [2v+o]
                    const float* __restrict__ lin_bias,
                    float* __restrict__ out)
{
    extern __shared__ char smem_raw[];
    SmemB* sm = (SmemB*)smem_raw;

    const int b    = blockIdx.x;
    const int tid  = threadIdx.x;
    const int wid  = tid >> 5;
    const int lane = tid & 31;

    // ---- stage (coalesced) ----
    {
        const uint4* src = (const uint4*)g_bits + (size_t)b * (BV * 4);
        uint4* dst = (uint4*)sm->bits;
        #pragma unroll
        for (int i = 0; i < 4; i++) dst[tid + i * NTHREADS] = src[tid + i * NTHREADS];

        sm->s2[tid]     = g_sxw[b * BV + tid];     // already dinv[w]-scaled
        sm->dinv_s[tid] = g_dinv[b * BV + tid];
        sm->lw2[tid]    = ((const float2*)lin_weight)[tid];
    }
    __syncthreads();

    // ---- build LUT: 2048 entries, 4 per thread ----
    #pragma unroll
    for (int i = 0; i < 4; i++) {
        int e = tid + i * NTHREADS;
        int pos = e >> 4, nib = e & 15;
        int l = pos >> 2, t = pos & 3;
        int j = l >> 1, h = l & 1;
        int wbase = 128 * (j >> 2) + 64 * h + 16 * t + (j & 3);
        float sx = 0.0f, sy = 0.0f;
        if (nib & 1) { float2 s = sm->s2[wbase];      sx += s.x; sy += s.y; }
        if (nib & 2) { float2 s = sm->s2[wbase + 4];  sx += s.x; sy += s.y; }
        if (nib & 4) { float2 s = sm->s2[wbase + 8];  sx += s.x; sy += s.y; }
        if (nib & 8) { float2 s = sm->s2[wbase + 12]; sx += s.x; sy += s.y; }
        unsigned long long packed;
        PACKX2(packed, __float_as_uint(sx), __float_as_uint(sy));
        sm->lut[pos * 17 + nib] = packed;
    }
    __syncthreads();

    const float cb0 = conv_bias[0];
    const float cb1 = conv_bias[1];
    const int q = lane >> 3;       // 0..3
    const int r = lane & 7;        // 0..7
    const int widx  = lane >> 1;          // mask word this lane reads
    const int shamt = (lane & 1) * 16;    // which half
    const int pbase17 = (lane * 4) * 17;  // lut row base for t=0

    float part = 0.0f;
    #pragma unroll
    for (int chunk = 0; chunk < 4; chunk++) {
        const int vbase = wid * 32 + chunk * 8;
        #pragma unroll
        for (int r8 = 0; r8 < 8; r8++) {
            unsigned word  = sm->bits[vbase + r8][widx];       // 2-way bcast LDS
            unsigned field = (word >> shamt) & 0xFFFFu;
            unsigned long long a0 = sm->lut[pbase17 +  0 + (field & 15)];
            unsigned long long a1 = sm->lut[pbase17 + 17 + ((field >> 4) & 15)];
            unsigned long long a2 = sm->lut[pbase17 + 34 + ((field >> 8) & 15)];
            unsigned long long a3 = sm->lut[pbase17 + 51 + (field >> 12)];
            ADDX2(a0, a0, a1);
            ADDX2(a2, a2, a3);
            ADDX2(a0, a0, a2);
            sm->buf[wid][r8][lane] = a0;
        }
        __syncwarp();

        // transpose-reduce: lane (q,r) sums 8 entries of row r
        unsigned long long s = sm->buf[wid][r][8 * q + 0];
        #pragma unroll
        for (int i = 1; i < 8; i++) {
            unsigned long long t = sm->buf[wid][r][8 * q + i];
            ADDX2(s, s, t);
        }
        unsigned lo_u, hi_u;
        UNPACKX2(lo_u, hi_u, s);
        float lo = __uint_as_float(lo_u), hi = __uint_as_float(hi_u);
        lo += __shfl_xor_sync(0xffffffffu, lo, 8);
        hi += __shfl_xor_sync(0xffffffffu, hi, 8);
        lo += __shfl_xor_sync(0xffffffffu, lo, 16);
        hi += __shfl_xor_sync(0xffffffffu, hi, 16);

        if (q == 0) {                       // lanes 0..7: rows vbase..vbase+7
            const int v = vbase + r;
            float d   = sm->dinv_s[v];
            float2 lw = sm->lw2[v];
            float h0 = fmaxf(fmaf(d, lo, cb0), 0.0f);
            float h1 = fmaxf(fmaf(d, hi, cb1), 0.0f);
            part = fmaf(h0, lw.x, part);
            part = fmaf(h1, lw.y, part);
        }
        __syncwarp();   // WAR on buf
    }

    // ---- final reduce + sigmoid ----
    #pragma unroll
    for (int sh = 16; sh; sh >>= 1) part += __shfl_xor_sync(0xffffffffu, part, sh);
    if (lane == 0) sm->wpart[wid] = part;
    __syncthreads();

    if (wid == 0) {
        float sdot = (lane < NWARP) ? sm->wpart[lane] : 0.0f;
        #pragma unroll
        for (int sh = 8; sh; sh >>= 1) sdot += __shfl_xor_sync(0xffffffffu, sdot, sh);
        if (lane == 0) {
            float logit = sdot + lin_bias[0];
            out[b] = 1.0f / (1.0f + expf(-logit));
        }
    }
}

extern "C" void kernel_launch(void* const* d_in, const int* in_sizes, int n_in,
                              void* d_out, int out_size) {
    const float* features    = (const float*)d_in[0];
    const int*   graphs      = (const int*)  d_in[1];
    const float* conv_weight = (const float*)d_in[2];
    const float* conv_bias   = (const float*)d_in[3];
    const float* lin_weight  = (const float*)d_in[4];
    const float* lin_bias    = (const float*)d_in[5];
    float* out = (float*)d_out;

    static int smem_set = 0;
    if (!smem_set) {
        cudaFuncSetAttribute(gcn_agg_kernel,
                             cudaFuncAttributeMaxDynamicSharedMemorySize,
                             (int)sizeof(SmemB));
        smem_set = 1;
    }

    gcn_rows_kernel<<<GRID_A, NTHREADS>>>(features, graphs, conv_weight);
    gcn_agg_kernel<<<BATCH, NTHREADS, sizeof(SmemB)>>>(conv_bias, lin_weight,
                                                       lin_bias, out);
}